// round 2
// baseline (speedup 1.0000x reference)
#include <cuda_runtime.h>
#include <cstdint>
#include <math_constants.h>

#define N_NODES 50000
#define N_EDGES 800000
#define IN_DIM 256
#define OUT_DIM 256
#define EDGE_DIM 128

// ---------------- device scratch (no allocations allowed) ----------------
__device__ __align__(16) float g_Y[(size_t)N_NODES * IN_DIM]; // Sum a_e * x[src]
__device__ float g_s[N_NODES];                    // per-node attention score part
__device__ float g_m[N_NODES];                    // segment max
__device__ float g_denom[N_NODES];                // segment sum of exp
__device__ float g_a[N_EDGES];                    // per-edge logit -> exp value
__device__ float g_wnatt[IN_DIM];                 // Wn^T @ attn
__device__ float g_weatt[EDGE_DIM];               // We^T @ attn
__device__ float g_batt[2];                       // [0]=bn.attn  [1]=be.attn
__device__ int   g_is64;                          // edge_index dtype flag

// ---------------- helpers ----------------
__device__ __forceinline__ void red_add_v4(float* p, float4 v) {
    asm volatile("red.global.add.v4.f32 [%0], {%1,%2,%3,%4};"
                 :: "l"(p), "f"(v.x), "f"(v.y), "f"(v.z), "f"(v.w)
                 : "memory");
}

__device__ __forceinline__ void atomicMaxFloat(float* addr, float value) {
    if (value >= 0.0f)
        atomicMax((int*)addr, __float_as_int(value));
    else
        atomicMin((unsigned int*)addr, __float_as_uint(value));
}

__device__ __forceinline__ int load_src(const int* ei, int e, int is64) {
    return is64 ? ei[2 * (size_t)e] : ei[e];
}
__device__ __forceinline__ int load_dst(const int* ei, int e, int is64) {
    return is64 ? ei[2 * (size_t)N_EDGES + 2 * (size_t)e] : ei[(size_t)N_EDGES + e];
}

// ---------------- K-detect: int64 vs int32 edge_index ----------------
__global__ void k_detect(const int* ei32) {
    // int64 node ids in [0, 2^31) -> every odd 32-bit word is 0.
    // For random int32 ids the probability all 64 sampled odd words are 0 is ~(1/N)^64 ~ 0.
    int allz = 1;
    for (int i = 0; i < 64; i++)
        if (ei32[2 * i + 1] != 0) allz = 0;
    g_is64 = allz;
}

// ---------------- K0a: tiny precompute of collapsed weight vectors ----------------
__global__ void k_prep(const float* __restrict__ Wn, const float* __restrict__ bn,
                       const float* __restrict__ We, const float* __restrict__ be,
                       const float* __restrict__ attn) {
    __shared__ float sa[256];
    int t = threadIdx.x;              // 256 threads
    sa[t] = attn[t];
    __syncthreads();
    float acc = 0.f;
    for (int i = 0; i < 256; i++) acc += sa[i] * Wn[(size_t)i * IN_DIM + t];
    g_wnatt[t] = acc;
    if (t < EDGE_DIM) {
        float ae = 0.f;
        for (int i = 0; i < 256; i++) ae += sa[i] * We[(size_t)i * EDGE_DIM + t];
        g_weatt[t] = ae;
    }
    if (t == 0) {
        float b1 = 0.f, b2 = 0.f;
        for (int i = 0; i < 256; i++) { b1 += sa[i] * bn[i]; b2 += sa[i] * be[i]; }
        g_batt[0] = b1; g_batt[1] = b2;
    }
}

// ---------------- K0b: init scratch ----------------
__global__ void k_init() {
    int i = blockIdx.x * blockDim.x + threadIdx.x;
    int stride = gridDim.x * blockDim.x;
    for (size_t j = i; j < (size_t)N_NODES * IN_DIM; j += stride) g_Y[j] = 0.f;
    if (i < N_NODES) { g_m[i] = -CUDART_INF_F; g_denom[i] = 0.f; }
}

// ---------------- K1: per-node score s[n] = x[n].wnatt + bn.attn ----------------
__global__ void k_score(const float* __restrict__ x) {
    __shared__ float sw[IN_DIM];
    int t = threadIdx.x;              // 256 threads
    sw[t] = g_wnatt[t];
    __syncthreads();
    int warp = t >> 5, lane = t & 31;
    int node = blockIdx.x * 8 + warp;
    if (node >= N_NODES) return;
    const float4* xr = (const float4*)(x + (size_t)node * IN_DIM);
    const float4* wr = (const float4*)sw;
    float acc = 0.f;
#pragma unroll
    for (int j = 0; j < 2; j++) {
        float4 v = xr[lane + 32 * j];
        float4 w = wr[lane + 32 * j];
        acc += v.x * w.x + v.y * w.y + v.z * w.z + v.w * w.w;
    }
#pragma unroll
    for (int o = 16; o; o >>= 1) acc += __shfl_xor_sync(0xFFFFFFFFu, acc, o);
    if (lane == 0) g_s[node] = acc + g_batt[0];
}

// ---------------- K2: edge logits + leaky relu + segment max ----------------
__global__ void k_logit(const float* __restrict__ ea, const int* __restrict__ ei) {
    __shared__ float sw[EDGE_DIM];
    int t = threadIdx.x;              // 256 threads
    if (t < EDGE_DIM) sw[t] = g_weatt[t];
    __syncthreads();
    int warp = t >> 5, lane = t & 31;
    int e = blockIdx.x * 8 + warp;
    if (e >= N_EDGES) return;
    float4 v = ((const float4*)(ea + (size_t)e * EDGE_DIM))[lane];
    float4 w = ((const float4*)sw)[lane];
    float acc = v.x * w.x + v.y * w.y + v.z * w.z + v.w * w.w;
#pragma unroll
    for (int o = 16; o; o >>= 1) acc += __shfl_xor_sync(0xFFFFFFFFu, acc, o);
    if (lane == 0) {
        int is64 = g_is64;
        int src = load_src(ei, e, is64);
        int dst = load_dst(ei, e, is64);
        float val = acc + g_s[src] + g_batt[1];
        val = val > 0.f ? val : 0.01f * val;       // leaky_relu
        g_a[e] = val;
        atomicMaxFloat(&g_m[dst], val);
    }
}

// ---------------- K3: exp(a - m[dst]) + segment sum ----------------
__global__ void k_expsum(const int* __restrict__ ei) {
    int e = blockIdx.x * blockDim.x + threadIdx.x;
    if (e >= N_EDGES) return;
    int dst = load_dst(ei, e, g_is64);
    float v = __expf(g_a[e] - g_m[dst]);
    g_a[e] = v;
    atomicAdd(&g_denom[dst], v);
}

// ---------------- K4: weighted scatter  Y[dst] += (a/denom) * x[src] ----------------
__global__ void k_scatter(const float* __restrict__ x, const int* __restrict__ ei) {
    int t = threadIdx.x;
    int warp = t >> 5, lane = t & 31;
    int e = blockIdx.x * 8 + warp;
    if (e >= N_EDGES) return;
    int is64 = g_is64;
    int src = load_src(ei, e, is64);
    int dst = load_dst(ei, e, is64);
    float w = g_a[e] / (g_denom[dst] + 1e-16f);
    const float4* xs = (const float4*)(x + (size_t)src * IN_DIM);
    float* yd = g_Y + (size_t)dst * IN_DIM;
#pragma unroll
    for (int j = 0; j < 2; j++) {
        float4 v = xs[lane + 32 * j];
        v.x *= w; v.y *= w; v.z *= w; v.w *= w;
        red_add_v4(yd + 4 * (lane + 32 * j), v);
    }
}

// ---------------- K5: out = relu(Y @ Wn^T + asum*bn)  (register-blocked fp32) ----------------
__global__ void k_gemm(const float* __restrict__ Wn, const float* __restrict__ bnv,
                       float* __restrict__ out) {
    const int BM = 128, BN = 64, BK = 32;
    __shared__ float As[BK][BM];
    __shared__ float Bs[BK][BN];
    int tid = threadIdx.x;            // 256 threads
    int bm = blockIdx.x * BM;
    int bnc = blockIdx.y * BN;
    int ty = tid >> 4;                // 0..15  (M dir, 8 rows each)
    int tx = tid & 15;                // 0..15  (N dir, 4 cols each)
    float acc[8][4] = {};

    for (int k0 = 0; k0 < IN_DIM; k0 += BK) {
        // load A tile (Y): 128 rows x 32 k -> 1024 float4 / 256 thr = 4 each
#pragma unroll
        for (int l = 0; l < 4; l++) {
            int idx = tid + l * 256;      // 0..1023
            int row = idx >> 3;           // 0..127
            int kq = idx & 7;             // float4 within the 32-float k slab
            float4 v = make_float4(0.f, 0.f, 0.f, 0.f);
            int gr = bm + row;
            if (gr < N_NODES)
                v = *(const float4*)(g_Y + (size_t)gr * IN_DIM + k0 + kq * 4);
            As[kq * 4 + 0][row] = v.x; As[kq * 4 + 1][row] = v.y;
            As[kq * 4 + 2][row] = v.z; As[kq * 4 + 3][row] = v.w;
        }
        // load B tile (Wn): 64 rows x 32 k -> 512 float4 / 256 thr = 2 each
#pragma unroll
        for (int l = 0; l < 2; l++) {
            int idx = tid + l * 256;      // 0..511
            int row = idx >> 3;           // 0..63
            int kq = idx & 7;
            float4 v = *(const float4*)(Wn + (size_t)(bnc + row) * IN_DIM + k0 + kq * 4);
            Bs[kq * 4 + 0][row] = v.x; Bs[kq * 4 + 1][row] = v.y;
            Bs[kq * 4 + 2][row] = v.z; Bs[kq * 4 + 3][row] = v.w;
        }
        __syncthreads();
#pragma unroll
        for (int kk = 0; kk < BK; kk++) {
            float a[8], b[4];
#pragma unroll
            for (int i = 0; i < 8; i++) a[i] = As[kk][ty * 8 + i];
#pragma unroll
            for (int j = 0; j < 4; j++) b[j] = Bs[kk][tx * 4 + j];
#pragma unroll
            for (int i = 0; i < 8; i++)
#pragma unroll
                for (int j = 0; j < 4; j++) acc[i][j] += a[i] * b[j];
        }
        __syncthreads();
    }

    // epilogue: + asum*bn, relu
#pragma unroll
    for (int i = 0; i < 8; i++) {
        int n = bm + ty * 8 + i;
        if (n >= N_NODES) continue;
        float d = g_denom[n];
        float as_ = d / (d + 1e-16f);    // == sum of normalized attention (0 if isolated)
#pragma unroll
        for (int j = 0; j < 4; j++) {
            int c = bnc + tx * 4 + j;
            float v = acc[i][j] + as_ * bnv[c];
            out[(size_t)n * OUT_DIM + c] = v > 0.f ? v : 0.f;
        }
    }
}

// ---------------- launch ----------------
extern "C" void kernel_launch(void* const* d_in, const int* in_sizes, int n_in,
                              void* d_out, int out_size) {
    const float* x    = (const float*)d_in[0];
    const int*   ei   = (const int*)d_in[1];   // int32 or int64 (auto-detected)
    const float* ea   = (const float*)d_in[2];
    const float* Wn   = (const float*)d_in[3];
    const float* bn   = (const float*)d_in[4];
    const float* We   = (const float*)d_in[5];
    const float* be   = (const float*)d_in[6];
    const float* attn = (const float*)d_in[7];
    float* out = (float*)d_out;

    k_detect<<<1, 1>>>(ei);
    k_prep<<<1, 256>>>(Wn, bn, We, be, attn);
    k_init<<<2048, 256>>>();
    k_score<<<(N_NODES + 7) / 8, 256>>>(x);
    k_logit<<<(N_EDGES + 7) / 8, 256>>>(ea, ei);
    k_expsum<<<(N_EDGES + 255) / 256, 256>>>(ei);
    k_scatter<<<(N_EDGES + 7) / 8, 256>>>(x, ei);
    dim3 g((N_NODES + 127) / 128, OUT_DIM / 64);
    k_gemm<<<g, 256>>>(Wn, bn, out);
}

// round 3
// speedup vs baseline: 1.2838x; 1.2838x over previous
#include <cuda_runtime.h>
#include <cstdint>
#include <math_constants.h>

#define N_NODES 50000
#define N_EDGES 800000
#define IN_DIM 256
#define OUT_DIM 256
#define EDGE_DIM 128

// ---------------- device scratch (no allocations allowed) ----------------
__device__ __align__(16) float g_Y[(size_t)N_NODES * IN_DIM]; // Sum a_e_norm * x[src]
__device__ float g_s[N_NODES];                    // per-node attention score part
__device__ float g_denom[N_NODES];                // segment sum of exp (for bias scale)
__device__ float g_as[N_EDGES];                   // logits, CSR-sorted by dst
__device__ int   g_epos[N_EDGES];                 // edge -> sorted position
__device__ int   g_esrc[N_EDGES];                 // CSR-sorted src ids
__device__ int   g_cnt[N_NODES];                  // histogram, then placement cursor
__device__ int   g_rowstart[N_NODES + 1];         // CSR row offsets
__device__ float g_wnatt[IN_DIM];                 // Wn^T @ attn
__device__ float g_weatt[EDGE_DIM];               // We^T @ attn
__device__ float g_batt[2];                       // [0]=bn.attn  [1]=be.attn
__device__ int   g_is64;                          // edge_index dtype flag

// ---------------- helpers ----------------
__device__ __forceinline__ int load_src(const int* ei, int e, int is64) {
    return is64 ? ei[2 * (size_t)e] : ei[e];
}
__device__ __forceinline__ int load_dst(const int* ei, int e, int is64) {
    return is64 ? ei[2 * (size_t)N_EDGES + 2 * (size_t)e] : ei[(size_t)N_EDGES + e];
}

// ---------------- K-detect: int64 vs int32 edge_index (parallel) ----------------
__global__ void k_detect(const int* ei32) {
    // int64 ids in [0,2^31) -> every odd 32-bit word is 0.
    int lane = threadIdx.x;            // 64 threads
    __shared__ int nz;
    if (lane == 0) nz = 0;
    __syncthreads();
    if (ei32[2 * lane + 1] != 0) atomicAdd(&nz, 1);
    __syncthreads();
    if (lane == 0) g_is64 = (nz == 0);
}

// ---------------- K-prep: collapsed weight vectors ----------------
__global__ void k_prep(const float* __restrict__ Wn, const float* __restrict__ bn,
                       const float* __restrict__ We, const float* __restrict__ be,
                       const float* __restrict__ attn) {
    __shared__ float sa[256];
    int t = threadIdx.x;               // 256 threads
    sa[t] = attn[t];
    __syncthreads();
    float acc = 0.f;
    for (int i = 0; i < 256; i++) acc += sa[i] * Wn[(size_t)i * IN_DIM + t];
    g_wnatt[t] = acc;
    if (t < EDGE_DIM) {
        float ae = 0.f;
        for (int i = 0; i < 256; i++) ae += sa[i] * We[(size_t)i * EDGE_DIM + t];
        g_weatt[t] = ae;
    }
    if (t == 0) {
        float b1 = 0.f, b2 = 0.f;
        for (int i = 0; i < 256; i++) { b1 += sa[i] * bn[i]; b2 += sa[i] * be[i]; }
        g_batt[0] = b1; g_batt[1] = b2;
    }
}

// ---------------- K-zero: reset histogram (must be deterministic per call) ----------------
__global__ void k_zero() {
    int i = blockIdx.x * blockDim.x + threadIdx.x;
    if (i < N_NODES) g_cnt[i] = 0;
}

// ---------------- K-score: s[n] = x[n].wnatt + bn.attn ----------------
__global__ void k_score(const float* __restrict__ x) {
    __shared__ float sw[IN_DIM];
    int t = threadIdx.x;               // 256 threads
    sw[t] = g_wnatt[t];
    __syncthreads();
    int warp = t >> 5, lane = t & 31;
    int node = blockIdx.x * 8 + warp;
    if (node >= N_NODES) return;
    const float4* xr = (const float4*)(x + (size_t)node * IN_DIM);
    const float4* wr = (const float4*)sw;
    float acc = 0.f;
#pragma unroll
    for (int j = 0; j < 2; j++) {
        float4 v = xr[lane + 32 * j];
        float4 w = wr[lane + 32 * j];
        acc += v.x * w.x + v.y * w.y + v.z * w.z + v.w * w.w;
    }
#pragma unroll
    for (int o = 16; o; o >>= 1) acc += __shfl_xor_sync(0xFFFFFFFFu, acc, o);
    if (lane == 0) g_s[node] = acc + g_batt[0];
}

// ---------------- K-hist: count edges per dst ----------------
__global__ void k_hist(const int* __restrict__ ei) {
    int e = blockIdx.x * blockDim.x + threadIdx.x;
    if (e >= N_EDGES) return;
    atomicAdd(&g_cnt[load_dst(ei, e, g_is64)], 1);
}

// ---------------- K-scan: exclusive prefix over counts -> rowstart; zero counts ----------------
__global__ void k_scan() {
    __shared__ int ws[32];
    __shared__ int carry, chunk_tot;
    int tid = threadIdx.x, lane = tid & 31, wid = tid >> 5;  // 1024 threads
    if (tid == 0) { carry = 0; }
    __syncthreads();
    for (int base = 0; base < N_NODES; base += 1024) {
        int i = base + tid;
        int v = (i < N_NODES) ? g_cnt[i] : 0;
        if (i < N_NODES) g_cnt[i] = 0;              // reset cursor for k_place
        int incl = v;
#pragma unroll
        for (int o = 1; o < 32; o <<= 1) {
            int t2 = __shfl_up_sync(0xFFFFFFFFu, incl, o);
            if (lane >= o) incl += t2;
        }
        if (lane == 31) ws[wid] = incl;
        __syncthreads();
        if (wid == 0) {
            int wv = ws[lane];
            int wincl = wv;
#pragma unroll
            for (int o = 1; o < 32; o <<= 1) {
                int t2 = __shfl_up_sync(0xFFFFFFFFu, wincl, o);
                if (lane >= o) wincl += t2;
            }
            ws[lane] = wincl - wv;                   // exclusive warp offsets
            if (lane == 31) chunk_tot = wincl;
        }
        __syncthreads();
        if (i < N_NODES) g_rowstart[i] = incl - v + ws[wid] + carry;
        __syncthreads();
        if (tid == 0) carry += chunk_tot;
        __syncthreads();
    }
    if (tid == 0) g_rowstart[N_NODES] = N_EDGES;
}

// ---------------- K-place: counting-sort placement ----------------
__global__ void k_place(const int* __restrict__ ei) {
    int e = blockIdx.x * blockDim.x + threadIdx.x;
    if (e >= N_EDGES) return;
    int is64 = g_is64;
    int dst = load_dst(ei, e, is64);
    int src = load_src(ei, e, is64);
    int pos = g_rowstart[dst] + atomicAdd(&g_cnt[dst], 1);
    g_epos[e] = pos;
    g_esrc[pos] = src;
}

// ---------------- K-logit: per-edge dot + leaky relu -> sorted slot (2 edges/warp) ----------------
__global__ void k_logit(const float* __restrict__ ea, const int* __restrict__ ei) {
    __shared__ float sw[EDGE_DIM];
    int t = threadIdx.x;               // 256 threads
    if (t < EDGE_DIM) sw[t] = g_weatt[t];
    __syncthreads();
    int warp = t >> 5, lane = t & 31;
    int e0 = (blockIdx.x * 8 + warp) * 2;
    if (e0 >= N_EDGES) return;
    float4 w4 = ((const float4*)sw)[lane];
    const float4* ea4 = (const float4*)ea;
    float4 u = ea4[(size_t)e0 * 32 + lane];
    float4 v = ea4[(size_t)(e0 + 1) * 32 + lane];  // N_EDGES even
    float d0 = u.x * w4.x + u.y * w4.y + u.z * w4.z + u.w * w4.w;
    float d1 = v.x * w4.x + v.y * w4.y + v.z * w4.z + v.w * w4.w;
#pragma unroll
    for (int o = 16; o; o >>= 1) {
        d0 += __shfl_xor_sync(0xFFFFFFFFu, d0, o);
        d1 += __shfl_xor_sync(0xFFFFFFFFu, d1, o);
    }
    if (lane < 2) {
        int e = e0 + lane;
        float dv = lane ? d1 : d0;
        int is64 = g_is64;
        int src = load_src(ei, e, is64);
        float val = dv + g_s[src] + g_batt[1];
        val = val > 0.f ? val : 0.01f * val;        // leaky_relu
        g_as[g_epos[e]] = val;
    }
}

// ---------------- K-node: per-node softmax + weighted gather (warp per node) ----------------
__global__ __launch_bounds__(256) void k_node(const float* __restrict__ x) {
    int t = threadIdx.x, warp = t >> 5, lane = t & 31;
    int n = blockIdx.x * 8 + warp;
    if (n >= N_NODES) return;
    int beg = g_rowstart[n], end = g_rowstart[n + 1];

    float m = -CUDART_INF_F;
    for (int i = beg + lane; i < end; i += 32) m = fmaxf(m, g_as[i]);
#pragma unroll
    for (int o = 16; o; o >>= 1) m = fmaxf(m, __shfl_xor_sync(0xFFFFFFFFu, m, o));

    float s = 0.f;
    for (int i = beg + lane; i < end; i += 32) s += __expf(g_as[i] - m);
#pragma unroll
    for (int o = 16; o; o >>= 1) s += __shfl_xor_sync(0xFFFFFFFFu, s, o);
    if (lane == 0) g_denom[n] = s;
    float inv = 1.f / (s + 1e-16f);

    float4 acc0 = make_float4(0.f, 0.f, 0.f, 0.f);
    float4 acc1 = make_float4(0.f, 0.f, 0.f, 0.f);
    for (int c = beg; c < end; c += 32) {
        int nc = min(32, end - c);
        float wv = 0.f; int sv = 0;
        if (lane < nc) {
            wv = __expf(g_as[c + lane] - m) * inv;
            sv = g_esrc[c + lane];
        }
        for (int k = 0; k < nc; k++) {
            float w = __shfl_sync(0xFFFFFFFFu, wv, k);
            int src = __shfl_sync(0xFFFFFFFFu, sv, k);
            const float4* xs = (const float4*)(x + (size_t)src * IN_DIM);
            float4 v0 = xs[lane], v1 = xs[lane + 32];
            acc0.x += w * v0.x; acc0.y += w * v0.y; acc0.z += w * v0.z; acc0.w += w * v0.w;
            acc1.x += w * v1.x; acc1.y += w * v1.y; acc1.z += w * v1.z; acc1.w += w * v1.w;
        }
    }
    float4* yd = (float4*)(g_Y + (size_t)n * IN_DIM);
    yd[lane] = acc0;
    yd[lane + 32] = acc1;
}

// ---------------- K-gemm: out = relu(Y @ Wn^T + asum*bn), packed f32x2 FMA ----------------
#define BM 128
#define BN 128
#define BK 32
__global__ __launch_bounds__(256, 2) void k_gemm(const float* __restrict__ Wn,
                                                 const float* __restrict__ bnv,
                                                 float* __restrict__ out) {
    __shared__ float As[BK][BM + 4];
    __shared__ float Bs[BK][BN + 4];
    int tid = threadIdx.x;             // 256 threads
    int bm = blockIdx.x * BM;
    int bnc = blockIdx.y * BN;
    int ty = tid >> 4;                 // 0..15 (8 rows each)
    int tx = tid & 15;                 // 0..15 (8 cols each, as 4 f32x2 pairs)

    unsigned long long acc[8][4];
#pragma unroll
    for (int i = 0; i < 8; i++)
#pragma unroll
        for (int j = 0; j < 4; j++) acc[i][j] = 0ull;

    for (int k0 = 0; k0 < IN_DIM; k0 += BK) {
        // A tile: 128 rows x 32 k = 1024 float4 / 256 thr = 4 each
#pragma unroll
        for (int l = 0; l < 4; l++) {
            int idx = tid + l * 256;   // 0..1023
            int row = idx >> 3;        // 0..127
            int kq = idx & 7;
            float4 v = make_float4(0.f, 0.f, 0.f, 0.f);
            int gr = bm + row;
            if (gr < N_NODES)
                v = *(const float4*)(g_Y + (size_t)gr * IN_DIM + k0 + kq * 4);
            As[kq * 4 + 0][row] = v.x; As[kq * 4 + 1][row] = v.y;
            As[kq * 4 + 2][row] = v.z; As[kq * 4 + 3][row] = v.w;
        }
        // B tile: 128 rows x 32 k = 1024 float4 / 256 thr = 4 each
#pragma unroll
        for (int l = 0; l < 4; l++) {
            int idx = tid + l * 256;
            int row = idx >> 3;
            int kq = idx & 7;
            float4 v = *(const float4*)(Wn + (size_t)(bnc + row) * IN_DIM + k0 + kq * 4);
            Bs[kq * 4 + 0][row] = v.x; Bs[kq * 4 + 1][row] = v.y;
            Bs[kq * 4 + 2][row] = v.z; Bs[kq * 4 + 3][row] = v.w;
        }
        __syncthreads();
#pragma unroll
        for (int kk = 0; kk < BK; kk++) {
            float4 a0 = *(const float4*)&As[kk][ty * 8];
            float4 a1 = *(const float4*)&As[kk][ty * 8 + 4];
            unsigned long long bp[4];
#pragma unroll
            for (int j = 0; j < 4; j++)
                bp[j] = *(const unsigned long long*)&Bs[kk][tx * 8 + 2 * j];
            float av[8] = {a0.x, a0.y, a0.z, a0.w, a1.x, a1.y, a1.z, a1.w};
#pragma unroll
            for (int i = 0; i < 8; i++) {
                unsigned long long aa;
                asm("mov.b64 %0, {%1, %1};" : "=l"(aa) : "f"(av[i]));
#pragma unroll
                for (int j = 0; j < 4; j++)
                    asm("fma.rn.f32x2 %0, %1, %2, %0;"
                        : "+l"(acc[i][j]) : "l"(aa), "l"(bp[j]));
            }
        }
        __syncthreads();
    }

    // epilogue: + asum*bn, relu
#pragma unroll
    for (int i = 0; i < 8; i++) {
        int n = bm + ty * 8 + i;
        if (n >= N_NODES) continue;
        float d = g_denom[n];
        float as_ = d / (d + 1e-16f);   // sum of normalized attention (0 if isolated)
#pragma unroll
        for (int j = 0; j < 4; j++) {
            int c = bnc + tx * 8 + 2 * j;
            float lo, hi;
            asm("mov.b64 {%0, %1}, %2;" : "=f"(lo), "=f"(hi) : "l"(acc[i][j]));
            float v0 = lo + as_ * bnv[c];
            float v1 = hi + as_ * bnv[c + 1];
            float2 o2 = make_float2(v0 > 0.f ? v0 : 0.f, v1 > 0.f ? v1 : 0.f);
            *(float2*)(out + (size_t)n * OUT_DIM + c) = o2;
        }
    }
}

// ---------------- launch ----------------
extern "C" void kernel_launch(void* const* d_in, const int* in_sizes, int n_in,
                              void* d_out, int out_size) {
    const float* x    = (const float*)d_in[0];
    const int*   ei   = (const int*)d_in[1];   // int32 or int64 (auto-detected)
    const float* ea   = (const float*)d_in[2];
    const float* Wn   = (const float*)d_in[3];
    const float* bn   = (const float*)d_in[4];
    const float* We   = (const float*)d_in[5];
    const float* be   = (const float*)d_in[6];
    const float* attn = (const float*)d_in[7];
    float* out = (float*)d_out;

    k_detect<<<1, 64>>>(ei);
    k_prep<<<1, 256>>>(Wn, bn, We, be, attn);
    k_zero<<<(N_NODES + 255) / 256, 256>>>();
    k_score<<<(N_NODES + 7) / 8, 256>>>(x);
    k_hist<<<(N_EDGES + 255) / 256, 256>>>(ei);
    k_scan<<<1, 1024>>>();
    k_place<<<(N_EDGES + 255) / 256, 256>>>(ei);
    k_logit<<<(N_EDGES + 15) / 16, 256>>>(ea, ei);
    k_node<<<(N_NODES + 7) / 8, 256>>>(x);
    dim3 g((N_NODES + BM - 1) / BM, OUT_DIM / BN);
    k_gemm<<<g, 256>>>(Wn, bn, out);
}

// round 5
// speedup vs baseline: 1.3570x; 1.0571x over previous
#include <cuda_runtime.h>
#include <cstdint>
#include <math_constants.h>

#define N_NODES 50000
#define N_EDGES 800000
#define IN_DIM 256
#define OUT_DIM 256
#define EDGE_DIM 128

// ---------------- device scratch (no allocations allowed) ----------------
__device__ __align__(16) float g_Y[(size_t)N_NODES * IN_DIM]; // Sum a_e_norm * x[src]
__device__ float g_s[N_NODES];                    // per-node attention score part
__device__ float g_denom[N_NODES];                // segment sum of exp (for bias scale)
__device__ float g_as[N_EDGES];                   // logits, CSR-sorted by dst
__device__ int   g_epos[N_EDGES];                 // edge -> sorted position
__device__ int   g_esrc[N_EDGES];                 // CSR-sorted src ids
__device__ int   g_cnt[N_NODES];                  // histogram, then placement cursor
__device__ int   g_rowstart[N_NODES + 1];         // CSR row offsets
__device__ float g_wnatt[IN_DIM];                 // Wn^T @ attn
__device__ float g_weatt[EDGE_DIM];               // We^T @ attn
__device__ float g_batt[2];                       // [0]=bn.attn  [1]=be.attn
__device__ int   g_is64;                          // edge_index dtype flag

// ---------------- helpers ----------------
__device__ __forceinline__ int load_src(const int* ei, int e, int is64) {
    return is64 ? ei[2 * (size_t)e] : ei[e];
}
__device__ __forceinline__ int load_dst(const int* ei, int e, int is64) {
    return is64 ? ei[2 * (size_t)N_EDGES + 2 * (size_t)e] : ei[(size_t)N_EDGES + e];
}

// ---------------- K-prep: dtype detect + collapsed weight vectors ----------------
__global__ void k_prep(const float* __restrict__ Wn, const float* __restrict__ bn,
                       const float* __restrict__ We, const float* __restrict__ be,
                       const float* __restrict__ attn, const int* __restrict__ ei32) {
    __shared__ float sa[256];
    __shared__ int nz;
    int t = threadIdx.x;               // 256 threads
    if (t == 0) nz = 0;
    sa[t] = attn[t];
    __syncthreads();
    // dtype detect: int64 ids in [0,2^31) -> every odd 32-bit word is 0
    if (t < 64 && ei32[2 * t + 1] != 0) atomicAdd(&nz, 1);
    float acc = 0.f;
    for (int i = 0; i < 256; i++) acc += sa[i] * Wn[(size_t)i * IN_DIM + t];
    g_wnatt[t] = acc;
    if (t < EDGE_DIM) {
        float ae = 0.f;
        for (int i = 0; i < 256; i++) ae += sa[i] * We[(size_t)i * EDGE_DIM + t];
        g_weatt[t] = ae;
    }
    __syncthreads();
    if (t == 0) {
        float b1 = 0.f, b2 = 0.f;
        for (int i = 0; i < 256; i++) { b1 += sa[i] * bn[i]; b2 += sa[i] * be[i]; }
        g_batt[0] = b1; g_batt[1] = b2;
        g_is64 = (nz == 0);
    }
}

// ---------------- K-score: s[n] = x[n].wnatt + bn.attn   (+ zero g_cnt) ----------------
__global__ void k_score(const float* __restrict__ x) {
    __shared__ float sw[IN_DIM];
    int t = threadIdx.x;               // 256 threads
    sw[t] = g_wnatt[t];
    // fused: zero histogram counters (first 196 blocks cover N_NODES)
    {
        int i = blockIdx.x * 256 + t;
        if (i < N_NODES && blockIdx.x < (N_NODES + 255) / 256) g_cnt[i] = 0;
    }
    __syncthreads();
    int warp = t >> 5, lane = t & 31;
    int node = blockIdx.x * 8 + warp;
    if (node >= N_NODES) return;
    const float4* xr = (const float4*)(x + (size_t)node * IN_DIM);
    const float4* wr = (const float4*)sw;
    float acc = 0.f;
#pragma unroll
    for (int j = 0; j < 2; j++) {
        float4 v = xr[lane + 32 * j];
        float4 w = wr[lane + 32 * j];
        acc += v.x * w.x + v.y * w.y + v.z * w.z + v.w * w.w;
    }
#pragma unroll
    for (int o = 16; o; o >>= 1) acc += __shfl_xor_sync(0xFFFFFFFFu, acc, o);
    if (lane == 0) g_s[node] = acc + g_batt[0];
}

// ---------------- K-hist: count edges per dst ----------------
__global__ void k_hist(const int* __restrict__ ei) {
    int e = blockIdx.x * blockDim.x + threadIdx.x;
    if (e >= N_EDGES) return;
    atomicAdd(&g_cnt[load_dst(ei, e, g_is64)], 1);
}

// ---------------- K-scan: exclusive prefix over counts -> rowstart; zero counts ----------------
__global__ void k_scan() {
    __shared__ int ws[32];
    __shared__ int carry, chunk_tot;
    int tid = threadIdx.x, lane = tid & 31, wid = tid >> 5;  // 1024 threads
    if (tid == 0) { carry = 0; }
    __syncthreads();
    for (int base = 0; base < N_NODES; base += 1024) {
        int i = base + tid;
        int v = (i < N_NODES) ? g_cnt[i] : 0;
        if (i < N_NODES) g_cnt[i] = 0;              // reset cursor for k_place
        int incl = v;
#pragma unroll
        for (int o = 1; o < 32; o <<= 1) {
            int t2 = __shfl_up_sync(0xFFFFFFFFu, incl, o);
            if (lane >= o) incl += t2;
        }
        if (lane == 31) ws[wid] = incl;
        __syncthreads();
        if (wid == 0) {
            int wv = ws[lane];
            int wincl = wv;
#pragma unroll
            for (int o = 1; o < 32; o <<= 1) {
                int t2 = __shfl_up_sync(0xFFFFFFFFu, wincl, o);
                if (lane >= o) wincl += t2;
            }
            ws[lane] = wincl - wv;                   // exclusive warp offsets
            if (lane == 31) chunk_tot = wincl;
        }
        __syncthreads();
        if (i < N_NODES) g_rowstart[i] = incl - v + ws[wid] + carry;
        __syncthreads();
        if (tid == 0) carry += chunk_tot;
        __syncthreads();
    }
    if (tid == 0) g_rowstart[N_NODES] = N_EDGES;
}

// ---------------- K-place: counting-sort placement ----------------
__global__ void k_place(const int* __restrict__ ei) {
    int e = blockIdx.x * blockDim.x + threadIdx.x;
    if (e >= N_EDGES) return;
    int is64 = g_is64;
    int dst = load_dst(ei, e, is64);
    int src = load_src(ei, e, is64);
    int pos = g_rowstart[dst] + atomicAdd(&g_cnt[dst], 1);
    g_epos[e] = pos;
    g_esrc[pos] = src;
}

// ---------------- K-logit: per-edge dot + leaky relu -> sorted slot (4 edges/warp) ----------------
__global__ void k_logit(const float* __restrict__ ea, const int* __restrict__ ei) {
    __shared__ float sw[EDGE_DIM];
    int t = threadIdx.x;               // 256 threads
    if (t < EDGE_DIM) sw[t] = g_weatt[t];
    __syncthreads();
    int warp = t >> 5, lane = t & 31;
    int e0 = (blockIdx.x * 8 + warp) * 4;
    if (e0 >= N_EDGES) return;
    float4 w4 = ((const float4*)sw)[lane];
    const float4* ea4 = (const float4*)ea;
    float d[4];
#pragma unroll
    for (int j = 0; j < 4; j++) {
        float4 u = ea4[(size_t)(e0 + j) * 32 + lane];   // N_EDGES % 4 == 0
        d[j] = u.x * w4.x + u.y * w4.y + u.z * w4.z + u.w * w4.w;
    }
#pragma unroll
    for (int o = 16; o; o >>= 1)
#pragma unroll
        for (int j = 0; j < 4; j++) d[j] += __shfl_xor_sync(0xFFFFFFFFu, d[j], o);
    if (lane < 4) {
        int e = e0 + lane;
        float dv = d[lane];
        int is64 = g_is64;
        int src = load_src(ei, e, is64);
        float val = dv + g_s[src] + g_batt[1];
        val = val > 0.f ? val : 0.01f * val;        // leaky_relu
        g_as[g_epos[e]] = val;
    }
}

// ---------------- K-node: per-node softmax + weighted gather (warp per node) ----------------
__global__ __launch_bounds__(256) void k_node(const float* __restrict__ x) {
    int t = threadIdx.x, warp = t >> 5, lane = t & 31;
    int n = blockIdx.x * 8 + warp;
    if (n >= N_NODES) return;
    int beg = g_rowstart[n], end = g_rowstart[n + 1];

    float m = -CUDART_INF_F;
    for (int i = beg + lane; i < end; i += 32) m = fmaxf(m, g_as[i]);
#pragma unroll
    for (int o = 16; o; o >>= 1) m = fmaxf(m, __shfl_xor_sync(0xFFFFFFFFu, m, o));

    float s = 0.f;
    for (int i = beg + lane; i < end; i += 32) s += __expf(g_as[i] - m);
#pragma unroll
    for (int o = 16; o; o >>= 1) s += __shfl_xor_sync(0xFFFFFFFFu, s, o);
    if (lane == 0) g_denom[n] = s;
    float inv = 1.f / (s + 1e-16f);

    float4 acc0 = make_float4(0.f, 0.f, 0.f, 0.f);
    float4 acc1 = make_float4(0.f, 0.f, 0.f, 0.f);
    for (int c = beg; c < end; c += 32) {
        int nc = min(32, end - c);
        float wv = 0.f; int sv = 0;
        if (lane < nc) {
            wv = __expf(g_as[c + lane] - m) * inv;
            sv = g_esrc[c + lane];
        }
        int k = 0;
        for (; k + 2 <= nc; k += 2) {
            float w0 = __shfl_sync(0xFFFFFFFFu, wv, k);
            int  s0 = __shfl_sync(0xFFFFFFFFu, sv, k);
            float w1 = __shfl_sync(0xFFFFFFFFu, wv, k + 1);
            int  s1 = __shfl_sync(0xFFFFFFFFu, sv, k + 1);
            const float4* xa = (const float4*)(x + (size_t)s0 * IN_DIM);
            const float4* xb = (const float4*)(x + (size_t)s1 * IN_DIM);
            float4 a0 = xa[lane], a1 = xa[lane + 32];
            float4 b0 = xb[lane], b1 = xb[lane + 32];
            acc0.x += w0 * a0.x + w1 * b0.x; acc0.y += w0 * a0.y + w1 * b0.y;
            acc0.z += w0 * a0.z + w1 * b0.z; acc0.w += w0 * a0.w + w1 * b0.w;
            acc1.x += w0 * a1.x + w1 * b1.x; acc1.y += w0 * a1.y + w1 * b1.y;
            acc1.z += w0 * a1.z + w1 * b1.z; acc1.w += w0 * a1.w + w1 * b1.w;
        }
        if (k < nc) {
            float w0 = __shfl_sync(0xFFFFFFFFu, wv, k);
            int  s0 = __shfl_sync(0xFFFFFFFFu, sv, k);
            const float4* xa = (const float4*)(x + (size_t)s0 * IN_DIM);
            float4 a0 = xa[lane], a1 = xa[lane + 32];
            acc0.x += w0 * a0.x; acc0.y += w0 * a0.y; acc0.z += w0 * a0.z; acc0.w += w0 * a0.w;
            acc1.x += w0 * a1.x; acc1.y += w0 * a1.y; acc1.z += w0 * a1.z; acc1.w += w0 * a1.w;
        }
    }
    float4* yd = (float4*)(g_Y + (size_t)n * IN_DIM);
    yd[lane] = acc0;
    yd[lane + 32] = acc1;
}

// ---------------- K-gemm: out = relu(Y @ Wn^T + asum*bn), packed f32x2 FMA ----------------
#define BM 128
#define BN 128
#define BK 32
__global__ __launch_bounds__(256, 2) void k_gemm(const float* __restrict__ Wn,
                                                 const float* __restrict__ bnv,
                                                 float* __restrict__ out) {
    __shared__ float As[BK][BM + 4];
    __shared__ float Bs[BK][BN + 4];
    int tid = threadIdx.x;             // 256 threads
    int bm = blockIdx.x * BM;
    int bnc = blockIdx.y * BN;
    int ty = tid >> 4;                 // 0..15 (8 rows each)
    int tx = tid & 15;                 // 0..15 (8 cols each, as 4 f32x2 pairs)

    unsigned long long acc[8][4];
#pragma unroll
    for (int i = 0; i < 8; i++)
#pragma unroll
        for (int j = 0; j < 4; j++) acc[i][j] = 0ull;

    for (int k0 = 0; k0 < IN_DIM; k0 += BK) {
        // A tile: 128 rows x 32 k = 1024 float4 / 256 thr = 4 each
#pragma unroll
        for (int l = 0; l < 4; l++) {
            int idx = tid + l * 256;   // 0..1023
            int row = idx >> 3;        // 0..127
            int kq = idx & 7;
            float4 v = make_float4(0.f, 0.f, 0.f, 0.f);
            int gr = bm + row;
            if (gr < N_NODES)
                v = *(const float4*)(g_Y + (size_t)gr * IN_DIM + k0 + kq * 4);
            As[kq * 4 + 0][row] = v.x; As[kq * 4 + 1][row] = v.y;
            As[kq * 4 + 2][row] = v.z; As[kq * 4 + 3][row] = v.w;
        }
        // B tile: 128 rows x 32 k = 1024 float4 / 256 thr = 4 each
#pragma unroll
        for (int l = 0; l < 4; l++) {
            int idx = tid + l * 256;
            int row = idx >> 3;
            int kq = idx & 7;
            float4 v = *(const float4*)(Wn + (size_t)(bnc + row) * IN_DIM + k0 + kq * 4);
            Bs[kq * 4 + 0][row] = v.x; Bs[kq * 4 + 1][row] = v.y;
            Bs[kq * 4 + 2][row] = v.z; Bs[kq * 4 + 3][row] = v.w;
        }
        __syncthreads();
#pragma unroll
        for (int kk = 0; kk < BK; kk++) {
            float4 a0 = *(const float4*)&As[kk][ty * 8];
            float4 a1 = *(const float4*)&As[kk][ty * 8 + 4];
            unsigned long long bp[4];
#pragma unroll
            for (int j = 0; j < 4; j++)
                bp[j] = *(const unsigned long long*)&Bs[kk][tx * 8 + 2 * j];
            float av[8] = {a0.x, a0.y, a0.z, a0.w, a1.x, a1.y, a1.z, a1.w};
#pragma unroll
            for (int i = 0; i < 8; i++) {
                unsigned long long aa;
                asm("mov.b64 %0, {%1, %1};" : "=l"(aa) : "f"(av[i]));
#pragma unroll
                for (int j = 0; j < 4; j++)
                    asm("fma.rn.f32x2 %0, %1, %2, %0;"
                        : "+l"(acc[i][j]) : "l"(aa), "l"(bp[j]));
            }
        }
        __syncthreads();
    }

    // epilogue: + asum*bn, relu
#pragma unroll
    for (int i = 0; i < 8; i++) {
        int n = bm + ty * 8 + i;
        if (n >= N_NODES) continue;
        float d = g_denom[n];
        float as_ = d / (d + 1e-16f);   // sum of normalized attention (0 if isolated)
#pragma unroll
        for (int j = 0; j < 4; j++) {
            int c = bnc + tx * 8 + 2 * j;
            float lo, hi;
            asm("mov.b64 {%0, %1}, %2;" : "=f"(lo), "=f"(hi) : "l"(acc[i][j]));
            float v0 = lo + as_ * bnv[c];
            float v1 = hi + as_ * bnv[c + 1];
            float2 o2 = make_float2(v0 > 0.f ? v0 : 0.f, v1 > 0.f ? v1 : 0.f);
            *(float2*)(out + (size_t)n * OUT_DIM + c) = o2;
        }
    }
}

// ---------------- launch ----------------
extern "C" void kernel_launch(void* const* d_in, const int* in_sizes, int n_in,
                              void* d_out, int out_size) {
    const float* x    = (const float*)d_in[0];
    const int*   ei   = (const int*)d_in[1];   // int32 or int64 (auto-detected)
    const float* ea   = (const float*)d_in[2];
    const float* Wn   = (const float*)d_in[3];
    const float* bn   = (const float*)d_in[4];
    const float* We   = (const float*)d_in[5];
    const float* be   = (const float*)d_in[6];
    const float* attn = (const float*)d_in[7];
    float* out = (float*)d_out;

    k_prep<<<1, 256>>>(Wn, bn, We, be, attn, ei);
    k_score<<<(N_NODES + 7) / 8, 256>>>(x);
    k_hist<<<(N_EDGES + 255) / 256, 256>>>(ei);
    k_scan<<<1, 1024>>>();
    k_place<<<(N_EDGES + 255) / 256, 256>>>(ei);
    k_logit<<<(N_EDGES + 31) / 32, 256>>>(ea, ei);
    k_node<<<(N_NODES + 7) / 8, 256>>>(x);
    dim3 g((N_NODES + BM - 1) / BM, OUT_DIM / BN);
    k_gemm<<<g, 256>>>(Wn, bn, out);
}

// round 7
// speedup vs baseline: 1.5241x; 1.1231x over previous
#include <cuda_runtime.h>
#include <cstdint>
#include <math_constants.h>

#define N_NODES 50000
#define N_EDGES 800000
#define IN_DIM 256
#define OUT_DIM 256
#define EDGE_DIM 128
#define SCAN_BLK 1024
#define N_SCAN_BLOCKS ((N_NODES + SCAN_BLK - 1) / SCAN_BLK)   // 49

// ---------------- device scratch (no allocations allowed) ----------------
__device__ __align__(16) float g_Y[(size_t)N_NODES * IN_DIM]; // Sum a_e_norm * x[src]
__device__ float g_s[N_NODES];                    // per-node attention score part
__device__ float g_denom[N_NODES];                // segment sum of exp (for bias scale)
__device__ float g_as[N_EDGES];                   // logits, CSR-sorted by dst
__device__ int   g_epos[N_EDGES];                 // edge -> sorted position
__device__ int   g_esrc[N_EDGES];                 // CSR-sorted src ids
__device__ int   g_cnt[N_NODES];                  // histogram, then placement cursor
__device__ int   g_rowstart[N_NODES + 1];         // CSR row offsets
__device__ int   g_bsum[64];                      // per-scan-block totals
__device__ int   g_boff[64];                      // per-scan-block exclusive offsets
__device__ float g_wnatt[IN_DIM];                 // Wn^T @ attn
__device__ float g_weatt[EDGE_DIM];               // We^T @ attn
__device__ float g_batt[2];                       // [0]=bn.attn  [1]=be.attn
__device__ int   g_is64;                          // edge_index dtype flag

// ---------------- helpers ----------------
__device__ __forceinline__ int load_src(const int* ei, int e, int is64) {
    return is64 ? ei[2 * (size_t)e] : ei[e];
}
__device__ __forceinline__ int load_dst(const int* ei, int e, int is64) {
    return is64 ? ei[2 * (size_t)N_EDGES + 2 * (size_t)e] : ei[(size_t)N_EDGES + e];
}

// ---------------- K-prep: dtype detect + collapsed weight vectors ----------------
__global__ void k_prep(const float* __restrict__ Wn, const float* __restrict__ bn,
                       const float* __restrict__ We, const float* __restrict__ be,
                       const float* __restrict__ attn, const int* __restrict__ ei32) {
    __shared__ float sa[256];
    __shared__ int nz;
    int t = threadIdx.x;               // 256 threads
    if (t == 0) nz = 0;
    sa[t] = attn[t];
    __syncthreads();
    // dtype detect: int64 ids in [0,2^31) -> every odd 32-bit word is 0
    if (t < 64 && ei32[2 * t + 1] != 0) atomicAdd(&nz, 1);
    float acc = 0.f;
    for (int i = 0; i < 256; i++) acc += sa[i] * Wn[(size_t)i * IN_DIM + t];
    g_wnatt[t] = acc;
    if (t < EDGE_DIM) {
        float ae = 0.f;
        for (int i = 0; i < 256; i++) ae += sa[i] * We[(size_t)i * EDGE_DIM + t];
        g_weatt[t] = ae;
    }
    __syncthreads();
    if (t == 0) {
        float b1 = 0.f, b2 = 0.f;
        for (int i = 0; i < 256; i++) { b1 += sa[i] * bn[i]; b2 += sa[i] * be[i]; }
        g_batt[0] = b1; g_batt[1] = b2;
        g_is64 = (nz == 0);
    }
}

// ---------------- K-score: s[n] = x[n].wnatt + bn.attn   (+ zero g_cnt) ----------------
__global__ void k_score(const float* __restrict__ x) {
    __shared__ float sw[IN_DIM];
    int t = threadIdx.x;               // 256 threads
    sw[t] = g_wnatt[t];
    // fused: zero histogram counters (first 196 blocks cover N_NODES)
    {
        int i = blockIdx.x * 256 + t;
        if (i < N_NODES && blockIdx.x < (N_NODES + 255) / 256) g_cnt[i] = 0;
    }
    __syncthreads();
    int warp = t >> 5, lane = t & 31;
    int node = blockIdx.x * 8 + warp;
    if (node >= N_NODES) return;
    const float4* xr = (const float4*)(x + (size_t)node * IN_DIM);
    const float4* wr = (const float4*)sw;
    float acc = 0.f;
#pragma unroll
    for (int j = 0; j < 2; j++) {
        float4 v = xr[lane + 32 * j];
        float4 w = wr[lane + 32 * j];
        acc += v.x * w.x + v.y * w.y + v.z * w.z + v.w * w.w;
    }
#pragma unroll
    for (int o = 16; o; o >>= 1) acc += __shfl_xor_sync(0xFFFFFFFFu, acc, o);
    if (lane == 0) g_s[node] = acc + g_batt[0];
}

// ---------------- K-hist: count edges per dst ----------------
__global__ void k_hist(const int* __restrict__ ei) {
    int e = blockIdx.x * blockDim.x + threadIdx.x;
    if (e >= N_EDGES) return;
    atomicAdd(&g_cnt[load_dst(ei, e, g_is64)], 1);
}

// ---------------- K-scanA: per-block exclusive scan + block totals; zero cnt ----------------
__global__ void k_scanA() {
    __shared__ int ws[32];
    int tid = threadIdx.x, lane = tid & 31, wid = tid >> 5;  // 1024 threads
    int i = blockIdx.x * SCAN_BLK + tid;
    int v = (i < N_NODES) ? g_cnt[i] : 0;
    if (i < N_NODES) g_cnt[i] = 0;                 // reset cursor for k_place
    int incl = v;
#pragma unroll
    for (int o = 1; o < 32; o <<= 1) {
        int t2 = __shfl_up_sync(0xFFFFFFFFu, incl, o);
        if (lane >= o) incl += t2;
    }
    if (lane == 31) ws[wid] = incl;
    __syncthreads();
    if (wid == 0) {
        int wv = ws[lane];
        int wincl = wv;
#pragma unroll
        for (int o = 1; o < 32; o <<= 1) {
            int t2 = __shfl_up_sync(0xFFFFFFFFu, wincl, o);
            if (lane >= o) wincl += t2;
        }
        ws[lane] = wincl - wv;                     // exclusive warp offsets
        if (lane == 31) g_bsum[blockIdx.x] = wincl;
    }
    __syncthreads();
    if (i < N_NODES) g_rowstart[i] = incl - v + ws[wid];   // block-local exclusive
}

// ---------------- K-scanB: scan the 49 block totals ----------------
__global__ void k_scanB() {
    int lane = threadIdx.x;            // 32 threads
    int a = (lane < N_SCAN_BLOCKS) ? g_bsum[lane] : 0;
    int b = (lane + 32 < N_SCAN_BLOCKS) ? g_bsum[lane + 32] : 0;
    int ia = a;
#pragma unroll
    for (int o = 1; o < 32; o <<= 1) {
        int t2 = __shfl_up_sync(0xFFFFFFFFu, ia, o);
        if (lane >= o) ia += t2;
    }
    int Ta = __shfl_sync(0xFFFFFFFFu, ia, 31);
    int ib = b;
#pragma unroll
    for (int o = 1; o < 32; o <<= 1) {
        int t2 = __shfl_up_sync(0xFFFFFFFFu, ib, o);
        if (lane >= o) ib += t2;
    }
    if (lane < N_SCAN_BLOCKS) g_boff[lane] = ia - a;
    if (lane + 32 < N_SCAN_BLOCKS) g_boff[lane + 32] = Ta + ib - b;
    if (lane == 0) g_rowstart[N_NODES] = N_EDGES;
}

// ---------------- K-scanC: add block offsets ----------------
__global__ void k_scanC() {
    int i = blockIdx.x * blockDim.x + threadIdx.x;
    if (i < N_NODES) g_rowstart[i] += g_boff[i >> 10];
}

// ---------------- K-place: counting-sort placement ----------------
__global__ void k_place(const int* __restrict__ ei) {
    int e = blockIdx.x * blockDim.x + threadIdx.x;
    if (e >= N_EDGES) return;
    int is64 = g_is64;
    int dst = load_dst(ei, e, is64);
    int src = load_src(ei, e, is64);
    int pos = g_rowstart[dst] + atomicAdd(&g_cnt[dst], 1);
    g_epos[e] = pos;
    g_esrc[pos] = src;
}

// ---------------- K-logit: per-edge dot + leaky relu -> sorted slot (4 edges/warp) ----------------
__global__ void k_logit(const float* __restrict__ ea, const int* __restrict__ ei) {
    __shared__ float sw[EDGE_DIM];
    int t = threadIdx.x;               // 256 threads
    if (t < EDGE_DIM) sw[t] = g_weatt[t];
    __syncthreads();
    int warp = t >> 5, lane = t & 31;
    int e0 = (blockIdx.x * 8 + warp) * 4;
    if (e0 >= N_EDGES) return;
    float4 w4 = ((const float4*)sw)[lane];
    const float4* ea4 = (const float4*)ea;
    float d[4];
#pragma unroll
    for (int j = 0; j < 4; j++) {
        float4 u = ea4[(size_t)(e0 + j) * 32 + lane];   // N_EDGES % 4 == 0
        d[j] = u.x * w4.x + u.y * w4.y + u.z * w4.z + u.w * w4.w;
    }
#pragma unroll
    for (int o = 16; o; o >>= 1)
#pragma unroll
        for (int j = 0; j < 4; j++) d[j] += __shfl_xor_sync(0xFFFFFFFFu, d[j], o);
    if (lane < 4) {
        int e = e0 + lane;
        float dv = d[lane];
        int is64 = g_is64;
        int src = load_src(ei, e, is64);
        float val = dv + g_s[src] + g_batt[1];
        val = val > 0.f ? val : 0.01f * val;        // leaky_relu
        g_as[g_epos[e]] = val;
    }
}

// ---------------- K-node: per-node softmax + weighted gather (warp per node) ----------------
__global__ __launch_bounds__(256) void k_node(const float* __restrict__ x) {
    int t = threadIdx.x, warp = t >> 5, lane = t & 31;
    int n = blockIdx.x * 8 + warp;
    if (n >= N_NODES) return;
    int beg = g_rowstart[n], end = g_rowstart[n + 1];

    float m = -CUDART_INF_F;
    for (int i = beg + lane; i < end; i += 32) m = fmaxf(m, g_as[i]);
#pragma unroll
    for (int o = 16; o; o >>= 1) m = fmaxf(m, __shfl_xor_sync(0xFFFFFFFFu, m, o));

    float s = 0.f;
    for (int i = beg + lane; i < end; i += 32) s += __expf(g_as[i] - m);
#pragma unroll
    for (int o = 16; o; o >>= 1) s += __shfl_xor_sync(0xFFFFFFFFu, s, o);
    if (lane == 0) g_denom[n] = s;
    float inv = 1.f / (s + 1e-16f);

    float4 acc0 = make_float4(0.f, 0.f, 0.f, 0.f);
    float4 acc1 = make_float4(0.f, 0.f, 0.f, 0.f);
    for (int c = beg; c < end; c += 32) {
        int nc = min(32, end - c);
        float wv = 0.f; int sv = 0;
        if (lane < nc) {
            wv = __expf(g_as[c + lane] - m) * inv;
            sv = g_esrc[c + lane];
        }
        int k = 0;
        for (; k + 2 <= nc; k += 2) {
            float w0 = __shfl_sync(0xFFFFFFFFu, wv, k);
            int  s0 = __shfl_sync(0xFFFFFFFFu, sv, k);
            float w1 = __shfl_sync(0xFFFFFFFFu, wv, k + 1);
            int  s1 = __shfl_sync(0xFFFFFFFFu, sv, k + 1);
            const float4* xa = (const float4*)(x + (size_t)s0 * IN_DIM);
            const float4* xb = (const float4*)(x + (size_t)s1 * IN_DIM);
            float4 a0 = xa[lane], a1 = xa[lane + 32];
            float4 b0 = xb[lane], b1 = xb[lane + 32];
            acc0.x += w0 * a0.x + w1 * b0.x; acc0.y += w0 * a0.y + w1 * b0.y;
            acc0.z += w0 * a0.z + w1 * b0.z; acc0.w += w0 * a0.w + w1 * b0.w;
            acc1.x += w0 * a1.x + w1 * b1.x; acc1.y += w0 * a1.y + w1 * b1.y;
            acc1.z += w0 * a1.z + w1 * b1.z; acc1.w += w0 * a1.w + w1 * b1.w;
        }
        if (k < nc) {
            float w0 = __shfl_sync(0xFFFFFFFFu, wv, k);
            int  s0 = __shfl_sync(0xFFFFFFFFu, sv, k);
            const float4* xa = (const float4*)(x + (size_t)s0 * IN_DIM);
            float4 a0 = xa[lane], a1 = xa[lane + 32];
            acc0.x += w0 * a0.x; acc0.y += w0 * a0.y; acc0.z += w0 * a0.z; acc0.w += w0 * a0.w;
            acc1.x += w0 * a1.x; acc1.y += w0 * a1.y; acc1.z += w0 * a1.z; acc1.w += w0 * a1.w;
        }
    }
    float4* yd = (float4*)(g_Y + (size_t)n * IN_DIM);
    yd[lane] = acc0;
    yd[lane + 32] = acc1;
}

// ---------------- K-gemm: out = relu(Y @ Wn^T + asum*bn), packed f32x2 FMA ----------------
#define BM 128
#define BN 128
#define BK 32
__global__ __launch_bounds__(256, 2) void k_gemm(const float* __restrict__ Wn,
                                                 const float* __restrict__ bnv,
                                                 float* __restrict__ out) {
    __shared__ float As[BK][BM + 4];
    __shared__ float Bs[BK][BN + 4];
    int tid = threadIdx.x;             // 256 threads
    int bm = blockIdx.x * BM;
    int bnc = blockIdx.y * BN;
    int ty = tid >> 4;                 // 0..15 (8 rows each)
    int tx = tid & 15;                 // 0..15 (8 cols each, as 4 f32x2 pairs)

    unsigned long long acc[8][4];
#pragma unroll
    for (int i = 0; i < 8; i++)
#pragma unroll
        for (int j = 0; j < 4; j++) acc[i][j] = 0ull;

    for (int k0 = 0; k0 < IN_DIM; k0 += BK) {
        // A tile: 128 rows x 32 k = 1024 float4 / 256 thr = 4 each
#pragma unroll
        for (int l = 0; l < 4; l++) {
            int idx = tid + l * 256;   // 0..1023
            int row = idx >> 3;        // 0..127
            int kq = idx & 7;
            float4 v = make_float4(0.f, 0.f, 0.f, 0.f);
            int gr = bm + row;
            if (gr < N_NODES)
                v = *(const float4*)(g_Y + (size_t)gr * IN_DIM + k0 + kq * 4);
            As[kq * 4 + 0][row] = v.x; As[kq * 4 + 1][row] = v.y;
            As[kq * 4 + 2][row] = v.z; As[kq * 4 + 3][row] = v.w;
        }
        // B tile: 128 rows x 32 k = 1024 float4 / 256 thr = 4 each
#pragma unroll
        for (int l = 0; l < 4; l++) {
            int idx = tid + l * 256;
            int row = idx >> 3;
            int kq = idx & 7;
            float4 v = *(const float4*)(Wn + (size_t)(bnc + row) * IN_DIM + k0 + kq * 4);
            Bs[kq * 4 + 0][row] = v.x; Bs[kq * 4 + 1][row] = v.y;
            Bs[kq * 4 + 2][row] = v.z; Bs[kq * 4 + 3][row] = v.w;
        }
        __syncthreads();
#pragma unroll
        for (int kk = 0; kk < BK; kk++) {
            float4 a0 = *(const float4*)&As[kk][ty * 8];
            float4 a1 = *(const float4*)&As[kk][ty * 8 + 4];
            unsigned long long bp[4];
#pragma unroll
            for (int j = 0; j < 4; j++)
                bp[j] = *(const unsigned long long*)&Bs[kk][tx * 8 + 2 * j];
            float av[8] = {a0.x, a0.y, a0.z, a0.w, a1.x, a1.y, a1.z, a1.w};
#pragma unroll
            for (int i = 0; i < 8; i++) {
                unsigned long long aa;
                asm("mov.b64 %0, {%1, %1};" : "=l"(aa) : "f"(av[i]));
#pragma unroll
                for (int j = 0; j < 4; j++)
                    asm("fma.rn.f32x2 %0, %1, %2, %0;"
                        : "+l"(acc[i][j]) : "l"(aa), "l"(bp[j]));
            }
        }
        __syncthreads();
    }

    // epilogue: + asum*bn, relu
#pragma unroll
    for (int i = 0; i < 8; i++) {
        int n = bm + ty * 8 + i;
        if (n >= N_NODES) continue;
        float d = g_denom[n];
        float as_ = d / (d + 1e-16f);   // sum of normalized attention (0 if isolated)
#pragma unroll
        for (int j = 0; j < 4; j++) {
            int c = bnc + tx * 8 + 2 * j;
            float lo, hi;
            asm("mov.b64 {%0, %1}, %2;" : "=f"(lo), "=f"(hi) : "l"(acc[i][j]));
            float v0 = lo + as_ * bnv[c];
            float v1 = hi + as_ * bnv[c + 1];
            float2 o2 = make_float2(v0 > 0.f ? v0 : 0.f, v1 > 0.f ? v1 : 0.f);
            *(float2*)(out + (size_t)n * OUT_DIM + c) = o2;
        }
    }
}

// ---------------- launch ----------------
extern "C" void kernel_launch(void* const* d_in, const int* in_sizes, int n_in,
                              void* d_out, int out_size) {
    const float* x    = (const float*)d_in[0];
    const int*   ei   = (const int*)d_in[1];   // int32 or int64 (auto-detected)
    const float* ea   = (const float*)d_in[2];
    const float* Wn   = (const float*)d_in[3];
    const float* bn   = (const float*)d_in[4];
    const float* We   = (const float*)d_in[5];
    const float* be   = (const float*)d_in[6];
    const float* attn = (const float*)d_in[7];
    float* out = (float*)d_out;

    k_prep<<<1, 256>>>(Wn, bn, We, be, attn, ei);
    k_score<<<(N_NODES + 7) / 8, 256>>>(x);
    k_hist<<<(N_EDGES + 255) / 256, 256>>>(ei);
    k_scanA<<<N_SCAN_BLOCKS, SCAN_BLK>>>();
    k_scanB<<<1, 32>>>();
    k_scanC<<<(N_NODES + 1023) / 1024, 1024>>>();
    k_place<<<(N_EDGES + 255) / 256, 256>>>(ei);
    k_logit<<<(N_EDGES + 31) / 32, 256>>>(ea, ei);
    k_node<<<(N_NODES + 7) / 8, 256>>>(x);
    dim3 g((N_NODES + BM - 1) / BM, OUT_DIM / BN);
    k_gemm<<<g, 256>>>(Wn, bn, out);
}